// round 15
// baseline (speedup 1.0000x reference)
#include <cuda_runtime.h>
#include <cuda_bf16.h>
#include <cstdint>

// RNN_50036368998466 via warp-level HMMA (mma.sync m16n8k16 bf16).
// R15 = R14's deduped K=64 B-image ([Whi|Wlo], hi frags reused) + conflict-free
// epilogue, with R13's MMA interleaving restored: k-substep outermost, all C
// fragments innermost -> accumulator reuse distance 8 (R14's distance-2 chains
// serialized the tensor pipe: issue 44->37%, dur 83->97us).

typedef uint32_t u32;

__device__ __align__(16) float g_wbuf[240];
__constant__ __align__(16) float cbuf[240];
// cbuf: [0..31] wih, [32..63] bsum, [64..79] b1, [80..207] W2, [208..215] b2,
//       [216..223] W3, [224] b3
// B image (bf16, rows 128B): [0,4096)B Whh 32rows x K64; [4096+2048*t)B W1_t 16rows x K64
__device__ __align__(16) __nv_bfloat16 g_bimg[5120];   // 10240 bytes

__device__ __forceinline__ float tanh_fast(float x) {
    float t; asm("tanh.approx.f32 %0, %1;" : "=f"(t) : "f"(x));
    return t;
}
__device__ __forceinline__ u32 pack_bf16(float a, float b) {  // lo=a, hi=b
    u32 r; asm("cvt.rn.bf16x2.f32 %0, %1, %2;" : "=r"(r) : "f"(b), "f"(a));
    return r;
}
__device__ __forceinline__ void split4(float v0, float v1, float v2, float v3,
                                       u32& h01, u32& h23, u32& l01, u32& l23) {
    h01 = pack_bf16(v0, v1); h23 = pack_bf16(v2, v3);
    float f0 = __uint_as_float(h01 << 16), f1 = __uint_as_float(h01 & 0xffff0000u);
    float f2 = __uint_as_float(h23 << 16), f3 = __uint_as_float(h23 & 0xffff0000u);
    l01 = pack_bf16(v0 - f0, v1 - f1); l23 = pack_bf16(v2 - f2, v3 - f3);
}
__device__ __forceinline__ u32 smem_u32(const void* p) {
    u32 a;
    asm("{ .reg .u64 t; cvta.to.shared.u64 t, %1; cvt.u32.u64 %0, t; }" : "=r"(a) : "l"(p));
    return a;
}
__device__ __forceinline__ void ldsm4(u32 a, u32& r0, u32& r1, u32& r2, u32& r3) {
    asm volatile("ldmatrix.sync.aligned.m8n8.x4.shared.b16 {%0,%1,%2,%3}, [%4];"
                 : "=r"(r0), "=r"(r1), "=r"(r2), "=r"(r3) : "r"(a));
}
__device__ __forceinline__ void mma16816(float* c, const u32* a, u32 b0, u32 b1) {
    asm volatile("mma.sync.aligned.m16n8k16.row.col.f32.bf16.bf16.f32 "
                 "{%0,%1,%2,%3}, {%4,%5,%6,%7}, {%8,%9}, {%0,%1,%2,%3};"
                 : "+f"(c[0]), "+f"(c[1]), "+f"(c[2]), "+f"(c[3])
                 : "r"(a[0]), "r"(a[1]), "r"(a[2]), "r"(a[3]), "r"(b0), "r"(b1));
}

// ---------------- pack kernel ----------------
__global__ __launch_bounds__(128)
void pack_weights(const float* __restrict__ W_ih, const float* __restrict__ W_hh,
                  const float* __restrict__ b_ih, const float* __restrict__ b_hh,
                  const float* __restrict__ W1,   const float* __restrict__ b1,
                  const float* __restrict__ W2,   const float* __restrict__ b2,
                  const float* __restrict__ W3,   const float* __restrict__ b3) {
    const int tid = threadIdx.x;
    if (tid < 32) { g_wbuf[tid] = W_ih[tid]; g_wbuf[32 + tid] = b_ih[tid] + b_hh[tid]; }
    if (tid < 16) g_wbuf[64 + tid] = b1[tid];
    g_wbuf[80 + tid] = W2[tid];
    if (tid < 8) { g_wbuf[208 + tid] = b2[tid]; g_wbuf[216 + tid] = W3[tid]; }
    if (tid == 0) g_wbuf[224] = b3[0];

    // Whh-B [n][k], k<32 -> hi(Whh[n][k]); k in 32..63 -> lo(Whh[n][k-32])
    for (int i = tid; i < 32 * 64; i += 128) {
        int n = i >> 6, k = i & 63;
        float w = W_hh[n * 32 + (k & 31)];
        __nv_bfloat16 hi = __float2bfloat16(w);
        g_bimg[i] = (k < 32) ? hi : __float2bfloat16(w - __bfloat162float(hi));
    }
    // W1-B_t [n][k]: base value W1[n][32t + (k&31)], hi | lo
    for (int i = tid; i < 3 * 16 * 64; i += 128) {
        int t = i >> 10, r = i & 1023, n = r >> 6, k = r & 63;
        float w = W1[n * 96 + 32 * t + (k & 31)];
        __nv_bfloat16 hi = __float2bfloat16(w);
        g_bimg[2048 + i] = (k < 32) ? hi : __float2bfloat16(w - __bfloat162float(hi));
    }
}

// ---------------- main kernel ----------------
__global__ __launch_bounds__(128, 3)
void rnn_hmma(const float* __restrict__ x, float* __restrict__ out) {
    __shared__ __align__(16) __nv_bfloat16 sB[5120];   // 10240 B
    __shared__ float sWih[32], sBsum[32];
    __shared__ float sX[3][128];
    __shared__ __align__(16) float sO1[16 * 132];      // [col][row], conflict-free

    const int tid = threadIdx.x;
    {   // stage B (640 float4)
        const float4* src = reinterpret_cast<const float4*>(g_bimg);
        float4* dst = reinterpret_cast<float4*>(sB);
#pragma unroll
        for (int i = 0; i < 5; i++) dst[tid + i * 128] = src[tid + i * 128];
    }
    if (tid < 32) { sWih[tid] = cbuf[tid]; sBsum[tid] = cbuf[32 + tid]; }
    {
        const float* xe = x + 3 * (size_t)(blockIdx.x * 128 + tid);
        sX[0][tid] = xe[0]; sX[1][tid] = xe[1]; sX[2][tid] = xe[2];
    }
    __syncthreads();

    const int lane = tid & 31, w = tid >> 5;
    const int g = lane >> 2, t = lane & 3;

    float wihc[8], bsc[8];
#pragma unroll
    for (int nt = 0; nt < 4; nt++) {
        wihc[2 * nt]     = sWih[8 * nt + 2 * t];
        wihc[2 * nt + 1] = sWih[8 * nt + 2 * t + 1];
        bsc[2 * nt]      = sBsum[8 * nt + 2 * t];
        bsc[2 * nt + 1]  = sBsum[8 * nt + 2 * t + 1];
    }
    const int rr = 32 * w + g;
    float xr[3][4];
#pragma unroll
    for (int s = 0; s < 3; s++) {
        xr[s][0] = sX[s][rr];      xr[s][1] = sX[s][rr + 8];
        xr[s][2] = sX[s][rr + 16]; xr[s][3] = sX[s][rr + 24];
    }

    const u32 sBaddr = smem_u32(sB);
    const u32 boff = (u32)((((lane >> 4) & 1) * 8 + (lane & 7)) * 128 + ((lane >> 3) & 1) * 16);

    u32 Ah[2][8], Al[2][8];
    float O1[2][2][4];
    float Cr[2][4][4];
#pragma unroll
    for (int a = 0; a < 2; a++)
#pragma unroll
        for (int b = 0; b < 2; b++)
#pragma unroll
            for (int c = 0; c < 4; c++) O1[a][b][c] = 0.f;

    // ---- step 1: h1 in fragment positions ----
#pragma unroll
    for (int mt = 0; mt < 2; mt++) {
        float xq0 = xr[0][2 * mt], xq1 = xr[0][2 * mt + 1];
#pragma unroll
        for (int nt = 0; nt < 4; nt++) {
            float v0 = tanh_fast(fmaf(xq0, wihc[2 * nt],     bsc[2 * nt]));
            float v1 = tanh_fast(fmaf(xq0, wihc[2 * nt + 1], bsc[2 * nt + 1]));
            float v2 = tanh_fast(fmaf(xq1, wihc[2 * nt],     bsc[2 * nt]));
            float v3 = tanh_fast(fmaf(xq1, wihc[2 * nt + 1], bsc[2 * nt + 1]));
            int base = (nt >> 1) * 4 + (nt & 1) * 2;
            split4(v0, v1, v2, v3, Ah[mt][base], Ah[mt][base + 1], Al[mt][base], Al[mt][base + 1]);
        }
    }

// REC_GEMM: k-substep outermost, all 8 C frags innermost (reuse distance 8).
// bh[pair][0..3]=H0(kt0 hi), bh[pair][4..7]=H1(kt1 hi); then lo reloads.
#define REC_GEMM() do { \
    _Pragma("unroll") \
    for (int mt = 0; mt < 2; mt++) \
        _Pragma("unroll") \
        for (int nt = 0; nt < 4; nt++) \
            _Pragma("unroll") \
            for (int j = 0; j < 4; j++) Cr[mt][nt][j] = 0.f; \
    u32 bb[2][8]; \
    _Pragma("unroll") \
    for (int pr = 0; pr < 2; pr++) { \
        const u32 pb = sBaddr + (u32)(pr * 2048) + boff; \
        ldsm4(pb + 0,  bb[pr][0], bb[pr][1], bb[pr][2], bb[pr][3]); \
        ldsm4(pb + 32, bb[pr][4], bb[pr][5], bb[pr][6], bb[pr][7]); \
    } \
    _Pragma("unroll") \
    for (int ks = 0; ks < 4; ks++) { \
        const int ah = (ks >> 1);           /* 0: use Ah, 1: use Al */ \
        const int kb = (ks & 1) * 4;        /* A reg base / B H sel */ \
        _Pragma("unroll") \
        for (int mt = 0; mt < 2; mt++) { \
            const u32* A = ah ? &Al[mt][kb] : &Ah[mt][kb]; \
            _Pragma("unroll") \
            for (int pr = 0; pr < 2; pr++) { \
                mma16816(Cr[mt][2 * pr],     A, bb[pr][kb],     bb[pr][kb + 1]); \
                mma16816(Cr[mt][2 * pr + 1], A, bb[pr][kb + 2], bb[pr][kb + 3]); \
            } \
        } \
    } \
    _Pragma("unroll") \
    for (int pr = 0; pr < 2; pr++) { \
        const u32 pb = sBaddr + (u32)(pr * 2048) + boff; \
        ldsm4(pb + 64, bb[pr][0], bb[pr][1], bb[pr][2], bb[pr][3]); \
        ldsm4(pb + 96, bb[pr][4], bb[pr][5], bb[pr][6], bb[pr][7]); \
    } \
    _Pragma("unroll") \
    for (int ks = 0; ks < 2; ks++) { \
        const int kb = ks * 4; \
        _Pragma("unroll") \
        for (int mt = 0; mt < 2; mt++) { \
            _Pragma("unroll") \
            for (int pr = 0; pr < 2; pr++) { \
                mma16816(Cr[mt][2 * pr],     &Ah[mt][kb], bb[pr][kb],     bb[pr][kb + 1]); \
                mma16816(Cr[mt][2 * pr + 1], &Ah[mt][kb], bb[pr][kb + 2], bb[pr][kb + 3]); \
            } \
        } \
    } \
} while (0)

#define RELU_A() do { \
    _Pragma("unroll") \
    for (int mt = 0; mt < 2; mt++) \
        _Pragma("unroll") \
        for (int i = 0; i < 8; i++) { \
            u32 s = Ah[mt][i]; \
            u32 m = ((s >> 15) & 0x10001u) * 0xffffu; \
            Ah[mt][i] = s & ~m; \
            Al[mt][i] = Al[mt][i] & ~m; \
        } \
} while (0)

// FC1: k-substep outermost over the 4 O1 frags (reuse distance 4)
#define FC1_GEMM(step) do { \
    const u32 fb = sBaddr + (u32)(4096 + 2048 * (step)) + boff; \
    u32 bh[8], bl[8]; \
    ldsm4(fb + 0,  bh[0], bh[1], bh[2], bh[3]); \
    ldsm4(fb + 32, bh[4], bh[5], bh[6], bh[7]); \
    ldsm4(fb + 64, bl[0], bl[1], bl[2], bl[3]); \
    ldsm4(fb + 96, bl[4], bl[5], bl[6], bl[7]); \
    _Pragma("unroll") \
    for (int ks = 0; ks < 6; ks++) { \
        const int sel = ks >> 1;            /* 0:Ah*Bhi 1:Al*Bhi 2:Ah*Blo */ \
        const int kb = (ks & 1) * 4; \
        _Pragma("unroll") \
        for (int mt = 0; mt < 2; mt++) { \
            const u32* A = (sel == 1) ? &Al[mt][kb] : &Ah[mt][kb]; \
            const u32* Bv = (sel == 2) ? &bl[kb] : &bh[kb]; \
            mma16816(O1[mt][0], A, Bv[0], Bv[1]); \
            mma16816(O1[mt][1], A, Bv[2], Bv[3]); \
        } \
    } \
} while (0)

#define CONV(sidx) do { \
    _Pragma("unroll") \
    for (int mt = 0; mt < 2; mt++) { \
        float xq0 = xr[sidx][2 * mt], xq1 = xr[sidx][2 * mt + 1]; \
        _Pragma("unroll") \
        for (int nt = 0; nt < 4; nt++) { \
            float v0 = tanh_fast(Cr[mt][nt][0] + fmaf(xq0, wihc[2 * nt],     bsc[2 * nt])); \
            float v1 = tanh_fast(Cr[mt][nt][1] + fmaf(xq0, wihc[2 * nt + 1], bsc[2 * nt + 1])); \
            float v2 = tanh_fast(Cr[mt][nt][2] + fmaf(xq1, wihc[2 * nt],     bsc[2 * nt])); \
            float v3 = tanh_fast(Cr[mt][nt][3] + fmaf(xq1, wihc[2 * nt + 1], bsc[2 * nt + 1])); \
            int base = (nt >> 1) * 4 + (nt & 1) * 2; \
            split4(v0, v1, v2, v3, Ah[mt][base], Ah[mt][base + 1], Al[mt][base], Al[mt][base + 1]); \
        } \
    } \
} while (0)

    REC_GEMM();
    RELU_A();
    FC1_GEMM(0);

    CONV(1);
    REC_GEMM();
    RELU_A();
    FC1_GEMM(1);

    // step 3: relu(tanh(...)) directly
#pragma unroll
    for (int mt = 0; mt < 2; mt++) {
        float xq0 = xr[2][2 * mt], xq1 = xr[2][2 * mt + 1];
#pragma unroll
        for (int nt = 0; nt < 4; nt++) {
            float v0 = fmaxf(tanh_fast(Cr[mt][nt][0] + fmaf(xq0, wihc[2 * nt],     bsc[2 * nt])), 0.f);
            float v1 = fmaxf(tanh_fast(Cr[mt][nt][1] + fmaf(xq0, wihc[2 * nt + 1], bsc[2 * nt + 1])), 0.f);
            float v2 = fmaxf(tanh_fast(Cr[mt][nt][2] + fmaf(xq1, wihc[2 * nt],     bsc[2 * nt])), 0.f);
            float v3 = fmaxf(tanh_fast(Cr[mt][nt][3] + fmaf(xq1, wihc[2 * nt + 1], bsc[2 * nt + 1])), 0.f);
            int base = (nt >> 1) * 4 + (nt & 1) * 2;
            split4(v0, v1, v2, v3, Ah[mt][base], Ah[mt][base + 1], Al[mt][base], Al[mt][base + 1]);
        }
    }
    FC1_GEMM(2);

    // ---- epilogue: conflict-free transposed store [col][row], scalar fc2/fc3 ----
#pragma unroll
    for (int mt = 0; mt < 2; mt++)
#pragma unroll
        for (int nt = 0; nt < 2; nt++)
#pragma unroll
            for (int h = 0; h < 2; h++)
#pragma unroll
                for (int j = 0; j < 2; j++)
                    sO1[(8 * nt + 2 * t + j) * 132 + 32 * w + 16 * mt + 8 * h + g]
                        = O1[mt][nt][2 * h + j];
    __syncwarp();

    float o1f[16];
#pragma unroll
    for (int i = 0; i < 16; i++)
        o1f[i] = sO1[i * 132 + tid] + cbuf[64 + i];

    float acc = cbuf[224];
#pragma unroll
    for (int i = 0; i < 8; i++) {
        float s = cbuf[208 + i];
#pragma unroll
        for (int k = 0; k < 16; k++)
            s = fmaf(o1f[k], cbuf[80 + i * 16 + k], s);
        acc = fmaf(fmaxf(s, 0.0f), cbuf[216 + i], acc);
    }
    out[blockIdx.x * 128 + tid] = acc;
}

extern "C" void kernel_launch(void* const* d_in, const int* in_sizes, int n_in,
                              void* d_out, int out_size) {
    const float* x    = (const float*)d_in[0];
    const float* W_ih = (const float*)d_in[1];
    const float* W_hh = (const float*)d_in[2];
    const float* b_ih = (const float*)d_in[3];
    const float* b_hh = (const float*)d_in[4];
    const float* W1   = (const float*)d_in[5];
    const float* b1   = (const float*)d_in[6];
    const float* W2   = (const float*)d_in[7];
    const float* b2   = (const float*)d_in[8];
    const float* W3   = (const float*)d_in[9];
    const float* b3   = (const float*)d_in[10];
    float* out = (float*)d_out;

    const int B = in_sizes[0] / 3;   // 1048576 = 8192 * 128 exactly

    pack_weights<<<1, 128>>>(W_ih, W_hh, b_ih, b_hh, W1, b1, W2, b2, W3, b3);

    void* wbuf_dev = nullptr;
    cudaGetSymbolAddress(&wbuf_dev, g_wbuf);
    cudaMemcpyToSymbolAsync(cbuf, wbuf_dev, 240 * sizeof(float), 0,
                            cudaMemcpyDeviceToDevice, 0);

    rnn_hmma<<<B / 128, 128>>>(x, out);
}

// round 16
// speedup vs baseline: 1.3332x; 1.3332x over previous
#include <cuda_runtime.h>
#include <cuda_bf16.h>
#include <cstdint>

// RNN_50036368998466 via warp-level HMMA (mma.sync m16n8k16 bf16).
// R16: B-image XOR-swizzled (chunk c at row n stored at c^(n&7)) so every
// ldmatrix 8x8 matrix hits all 32 banks -> conflict-free (R14/15's 128B row
// stride put all 8 rows on one bank phase: 8-way conflicts, L1 84%).
// K=64 dedup ([Whi|Wlo], hi frags reused) + conflict-free epilogue retained.

typedef uint32_t u32;

__device__ __align__(16) float g_wbuf[240];
__constant__ __align__(16) float cbuf[240];
// cbuf: [0..31] wih, [32..63] bsum, [64..79] b1, [80..207] W2, [208..215] b2,
//       [216..223] W3, [224] b3
// B image (bf16, 128B rows, XOR-swizzled): [0,4096)B Whh 32rows x K64;
// [4096+2048*t)B W1_t 16rows x K64
__device__ __align__(16) __nv_bfloat16 g_bimg[5120];   // 10240 bytes

__device__ __forceinline__ float tanh_fast(float x) {
    float t; asm("tanh.approx.f32 %0, %1;" : "=f"(t) : "f"(x));
    return t;
}
__device__ __forceinline__ u32 pack_bf16(float a, float b) {  // lo=a, hi=b
    u32 r; asm("cvt.rn.bf16x2.f32 %0, %1, %2;" : "=r"(r) : "f"(b), "f"(a));
    return r;
}
__device__ __forceinline__ void split4(float v0, float v1, float v2, float v3,
                                       u32& h01, u32& h23, u32& l01, u32& l23) {
    h01 = pack_bf16(v0, v1); h23 = pack_bf16(v2, v3);
    float f0 = __uint_as_float(h01 << 16), f1 = __uint_as_float(h01 & 0xffff0000u);
    float f2 = __uint_as_float(h23 << 16), f3 = __uint_as_float(h23 & 0xffff0000u);
    l01 = pack_bf16(v0 - f0, v1 - f1); l23 = pack_bf16(v2 - f2, v3 - f3);
}
__device__ __forceinline__ u32 smem_u32(const void* p) {
    u32 a;
    asm("{ .reg .u64 t; cvta.to.shared.u64 t, %1; cvt.u32.u64 %0, t; }" : "=r"(a) : "l"(p));
    return a;
}
__device__ __forceinline__ void ldsm4(u32 a, u32& r0, u32& r1, u32& r2, u32& r3) {
    asm volatile("ldmatrix.sync.aligned.m8n8.x4.shared.b16 {%0,%1,%2,%3}, [%4];"
                 : "=r"(r0), "=r"(r1), "=r"(r2), "=r"(r3) : "r"(a));
}
__device__ __forceinline__ void mma16816(float* c, const u32* a, u32 b0, u32 b1) {
    asm volatile("mma.sync.aligned.m16n8k16.row.col.f32.bf16.bf16.f32 "
                 "{%0,%1,%2,%3}, {%4,%5,%6,%7}, {%8,%9}, {%0,%1,%2,%3};"
                 : "+f"(c[0]), "+f"(c[1]), "+f"(c[2]), "+f"(c[3])
                 : "r"(a[0]), "r"(a[1]), "r"(a[2]), "r"(a[3]), "r"(b0), "r"(b1));
}

// swizzled byte offset within a B-image region for element [n][k] (k<64)
__device__ __forceinline__ int bswz(int n, int k) {
    return n * 128 + ((((k >> 3) ^ (n & 7)) << 4) | ((k & 7) * 2));
}

// ---------------- pack kernel ----------------
__global__ __launch_bounds__(128)
void pack_weights(const float* __restrict__ W_ih, const float* __restrict__ W_hh,
                  const float* __restrict__ b_ih, const float* __restrict__ b_hh,
                  const float* __restrict__ W1,   const float* __restrict__ b1,
                  const float* __restrict__ W2,   const float* __restrict__ b2,
                  const float* __restrict__ W3,   const float* __restrict__ b3) {
    const int tid = threadIdx.x;
    if (tid < 32) { g_wbuf[tid] = W_ih[tid]; g_wbuf[32 + tid] = b_ih[tid] + b_hh[tid]; }
    if (tid < 16) g_wbuf[64 + tid] = b1[tid];
    g_wbuf[80 + tid] = W2[tid];
    if (tid < 8) { g_wbuf[208 + tid] = b2[tid]; g_wbuf[216 + tid] = W3[tid]; }
    if (tid == 0) g_wbuf[224] = b3[0];

    // Whh-B [n][k], k<32 -> hi(Whh[n][k]); k in 32..63 -> lo(Whh[n][k-32])
    for (int i = tid; i < 32 * 64; i += 128) {
        int n = i >> 6, k = i & 63;
        float w = W_hh[n * 32 + (k & 31)];
        __nv_bfloat16 hi = __float2bfloat16(w);
        g_bimg[bswz(n, k) >> 1] = (k < 32) ? hi : __float2bfloat16(w - __bfloat162float(hi));
    }
    // W1-B_t [n][k]: base W1[n][32t + (k&31)], hi | lo
    for (int i = tid; i < 3 * 16 * 64; i += 128) {
        int t = i >> 10, r = i & 1023, n = r >> 6, k = r & 63;
        float w = W1[n * 96 + 32 * t + (k & 31)];
        __nv_bfloat16 hi = __float2bfloat16(w);
        g_bimg[(4096 + 2048 * t + bswz(n, k)) >> 1]
            = (k < 32) ? hi : __float2bfloat16(w - __bfloat162float(hi));
    }
}

// ---------------- main kernel ----------------
__global__ __launch_bounds__(128, 3)
void rnn_hmma(const float* __restrict__ x, float* __restrict__ out) {
    __shared__ __align__(16) __nv_bfloat16 sB[5120];   // 10240 B
    __shared__ float sWih[32], sBsum[32];
    __shared__ float sX[3][128];
    __shared__ __align__(16) float sO1[16 * 132];      // [col][row], conflict-free

    const int tid = threadIdx.x;
    {   // stage B (640 float4)
        const float4* src = reinterpret_cast<const float4*>(g_bimg);
        float4* dst = reinterpret_cast<float4*>(sB);
#pragma unroll
        for (int i = 0; i < 5; i++) dst[tid + i * 128] = src[tid + i * 128];
    }
    if (tid < 32) { sWih[tid] = cbuf[tid]; sBsum[tid] = cbuf[32 + tid]; }
    {
        const float* xe = x + 3 * (size_t)(blockIdx.x * 128 + tid);
        sX[0][tid] = xe[0]; sX[1][tid] = xe[1]; sX[2][tid] = xe[2];
    }
    __syncthreads();

    const int lane = tid & 31, w = tid >> 5;
    const int g = lane >> 2, t = lane & 3;

    float wihc[8], bsc[8];
#pragma unroll
    for (int nt = 0; nt < 4; nt++) {
        wihc[2 * nt]     = sWih[8 * nt + 2 * t];
        wihc[2 * nt + 1] = sWih[8 * nt + 2 * t + 1];
        bsc[2 * nt]      = sBsum[8 * nt + 2 * t];
        bsc[2 * nt + 1]  = sBsum[8 * nt + 2 * t + 1];
    }
    const int rr = 32 * w + g;
    float xr[3][4];
#pragma unroll
    for (int s = 0; s < 3; s++) {
        xr[s][0] = sX[s][rr];      xr[s][1] = sX[s][rr + 8];
        xr[s][2] = sX[s][rr + 16]; xr[s][3] = sX[s][rr + 24];
    }

    // ldmatrix lane addressing with XOR swizzle:
    // this lane supplies the row address for matrix row nrow, k-chunk (cb + cpar)
    const u32 sBaddr = smem_u32(sB);
    const int nrow = ((lane >> 4) & 1) * 8 + (lane & 7);
    const int cpar = (lane >> 3) & 1;
    const u32 rbase = (u32)(nrow * 128);
    const u32 nx = (u32)(nrow & 7);
    // address of chunk-base cb (0,2,4,6) for this lane:
#define BADDR(region, cb) (sBaddr + (u32)(region) + rbase + ((((u32)(cb) + (u32)cpar) ^ nx) << 4))

    u32 Ah[2][8], Al[2][8];
    float O1[2][2][4];
    float Cr[2][4][4];
#pragma unroll
    for (int a = 0; a < 2; a++)
#pragma unroll
        for (int b = 0; b < 2; b++)
#pragma unroll
            for (int c = 0; c < 4; c++) O1[a][b][c] = 0.f;

    // ---- step 1: h1 in fragment positions ----
#pragma unroll
    for (int mt = 0; mt < 2; mt++) {
        float xq0 = xr[0][2 * mt], xq1 = xr[0][2 * mt + 1];
#pragma unroll
        for (int nt = 0; nt < 4; nt++) {
            float v0 = tanh_fast(fmaf(xq0, wihc[2 * nt],     bsc[2 * nt]));
            float v1 = tanh_fast(fmaf(xq0, wihc[2 * nt + 1], bsc[2 * nt + 1]));
            float v2 = tanh_fast(fmaf(xq1, wihc[2 * nt],     bsc[2 * nt]));
            float v3 = tanh_fast(fmaf(xq1, wihc[2 * nt + 1], bsc[2 * nt + 1]));
            int base = (nt >> 1) * 4 + (nt & 1) * 2;
            split4(v0, v1, v2, v3, Ah[mt][base], Ah[mt][base + 1], Al[mt][base], Al[mt][base + 1]);
        }
    }

#define REC_GEMM() do { \
    _Pragma("unroll") \
    for (int mt = 0; mt < 2; mt++) \
        _Pragma("unroll") \
        for (int nt = 0; nt < 4; nt++) \
            _Pragma("unroll") \
            for (int j = 0; j < 4; j++) Cr[mt][nt][j] = 0.f; \
    u32 bb[2][8]; \
    _Pragma("unroll") \
    for (int pr = 0; pr < 2; pr++) { \
        ldsm4(BADDR(pr * 2048, 0), bb[pr][0], bb[pr][1], bb[pr][2], bb[pr][3]); \
        ldsm4(BADDR(pr * 2048, 2), bb[pr][4], bb[pr][5], bb[pr][6], bb[pr][7]); \
    } \
    _Pragma("unroll") \
    for (int ks = 0; ks < 4; ks++) { \
        const int ah = (ks >> 1); \
        const int kb = (ks & 1) * 4; \
        _Pragma("unroll") \
        for (int mt = 0; mt < 2; mt++) { \
            const u32* A = ah ? &Al[mt][kb] : &Ah[mt][kb]; \
            _Pragma("unroll") \
            for (int pr = 0; pr < 2; pr++) { \
                mma16816(Cr[mt][2 * pr],     A, bb[pr][kb],     bb[pr][kb + 1]); \
                mma16816(Cr[mt][2 * pr + 1], A, bb[pr][kb + 2], bb[pr][kb + 3]); \
            } \
        } \
    } \
    _Pragma("unroll") \
    for (int pr = 0; pr < 2; pr++) { \
        ldsm4(BADDR(pr * 2048, 4), bb[pr][0], bb[pr][1], bb[pr][2], bb[pr][3]); \
        ldsm4(BADDR(pr * 2048, 6), bb[pr][4], bb[pr][5], bb[pr][6], bb[pr][7]); \
    } \
    _Pragma("unroll") \
    for (int ks = 0; ks < 2; ks++) { \
        const int kb = ks * 4; \
        _Pragma("unroll") \
        for (int mt = 0; mt < 2; mt++) { \
            _Pragma("unroll") \
            for (int pr = 0; pr < 2; pr++) { \
                mma16816(Cr[mt][2 * pr],     &Ah[mt][kb], bb[pr][kb],     bb[pr][kb + 1]); \
                mma16816(Cr[mt][2 * pr + 1], &Ah[mt][kb], bb[pr][kb + 2], bb[pr][kb + 3]); \
            } \
        } \
    } \
} while (0)

#define RELU_A() do { \
    _Pragma("unroll") \
    for (int mt = 0; mt < 2; mt++) \
        _Pragma("unroll") \
        for (int i = 0; i < 8; i++) { \
            u32 s = Ah[mt][i]; \
            u32 m = ((s >> 15) & 0x10001u) * 0xffffu; \
            Ah[mt][i] = s & ~m; \
            Al[mt][i] = Al[mt][i] & ~m; \
        } \
} while (0)

#define FC1_GEMM(step) do { \
    u32 bh[8], bl[8]; \
    ldsm4(BADDR(4096 + 2048 * (step), 0), bh[0], bh[1], bh[2], bh[3]); \
    ldsm4(BADDR(4096 + 2048 * (step), 2), bh[4], bh[5], bh[6], bh[7]); \
    ldsm4(BADDR(4096 + 2048 * (step), 4), bl[0], bl[1], bl[2], bl[3]); \
    ldsm4(BADDR(4096 + 2048 * (step), 6), bl[4], bl[5], bl[6], bl[7]); \
    _Pragma("unroll") \
    for (int ks = 0; ks < 6; ks++) { \
        const int sel = ks >> 1; \
        const int kb = (ks & 1) * 4; \
        _Pragma("unroll") \
        for (int mt = 0; mt < 2; mt++) { \
            const u32* A = (sel == 1) ? &Al[mt][kb] : &Ah[mt][kb]; \
            const u32* Bv = (sel == 2) ? &bl[kb] : &bh[kb]; \
            mma16816(O1[mt][0], A, Bv[0], Bv[1]); \
            mma16816(O1[mt][1], A, Bv[2], Bv[3]); \
        } \
    } \
} while (0)

#define CONV(sidx) do { \
    _Pragma("unroll") \
    for (int mt = 0; mt < 2; mt++) { \
        float xq0 = xr[sidx][2 * mt], xq1 = xr[sidx][2 * mt + 1]; \
        _Pragma("unroll") \
        for (int nt = 0; nt < 4; nt++) { \
            float v0 = tanh_fast(Cr[mt][nt][0] + fmaf(xq0, wihc[2 * nt],     bsc[2 * nt])); \
            float v1 = tanh_fast(Cr[mt][nt][1] + fmaf(xq0, wihc[2 * nt + 1], bsc[2 * nt + 1])); \
            float v2 = tanh_fast(Cr[mt][nt][2] + fmaf(xq1, wihc[2 * nt],     bsc[2 * nt])); \
            float v3 = tanh_fast(Cr[mt][nt][3] + fmaf(xq1, wihc[2 * nt + 1], bsc[2 * nt + 1])); \
            int base = (nt >> 1) * 4 + (nt & 1) * 2; \
            split4(v0, v1, v2, v3, Ah[mt][base], Ah[mt][base + 1], Al[mt][base], Al[mt][base + 1]); \
        } \
    } \
} while (0)

    REC_GEMM();
    RELU_A();
    FC1_GEMM(0);

    CONV(1);
    REC_GEMM();
    RELU_A();
    FC1_GEMM(1);

    // step 3: relu(tanh(...)) directly
#pragma unroll
    for (int mt = 0; mt < 2; mt++) {
        float xq0 = xr[2][2 * mt], xq1 = xr[2][2 * mt + 1];
#pragma unroll
        for (int nt = 0; nt < 4; nt++) {
            float v0 = fmaxf(tanh_fast(Cr[mt][nt][0] + fmaf(xq0, wihc[2 * nt],     bsc[2 * nt])), 0.f);
            float v1 = fmaxf(tanh_fast(Cr[mt][nt][1] + fmaf(xq0, wihc[2 * nt + 1], bsc[2 * nt + 1])), 0.f);
            float v2 = fmaxf(tanh_fast(Cr[mt][nt][2] + fmaf(xq1, wihc[2 * nt],     bsc[2 * nt])), 0.f);
            float v3 = fmaxf(tanh_fast(Cr[mt][nt][3] + fmaf(xq1, wihc[2 * nt + 1], bsc[2 * nt + 1])), 0.f);
            int base = (nt >> 1) * 4 + (nt & 1) * 2;
            split4(v0, v1, v2, v3, Ah[mt][base], Ah[mt][base + 1], Al[mt][base], Al[mt][base + 1]);
        }
    }
    FC1_GEMM(2);

    // ---- epilogue: conflict-free transposed store [col][row], scalar fc2/fc3 ----
#pragma unroll
    for (int mt = 0; mt < 2; mt++)
#pragma unroll
        for (int nt = 0; nt < 2; nt++)
#pragma unroll
            for (int h = 0; h < 2; h++)
#pragma unroll
                for (int j = 0; j < 2; j++)
                    sO1[(8 * nt + 2 * t + j) * 132 + 32 * w + 16 * mt + 8 * h + g]
                        = O1[mt][nt][2 * h + j];
    __syncwarp();

    float o1f[16];
#pragma unroll
    for (int i = 0; i < 16; i++)
        o1f[i] = sO1[i * 132 + tid] + cbuf[64 + i];

    float acc = cbuf[224];
#pragma unroll
    for (int i = 0; i < 8; i++) {
        float s = cbuf[208 + i];
#pragma unroll
        for (int k = 0; k < 16; k++)
            s = fmaf(o1f[k], cbuf[80 + i * 16 + k], s);
        acc = fmaf(fmaxf(s, 0.0f), cbuf[216 + i], acc);
    }
    out[blockIdx.x * 128 + tid] = acc;
}

extern "C" void kernel_launch(void* const* d_in, const int* in_sizes, int n_in,
                              void* d_out, int out_size) {
    const float* x    = (const float*)d_in[0];
    const float* W_ih = (const float*)d_in[1];
    const float* W_hh = (const float*)d_in[2];
    const float* b_ih = (const float*)d_in[3];
    const float* b_hh = (const float*)d_in[4];
    const float* W1   = (const float*)d_in[5];
    const float* b1   = (const float*)d_in[6];
    const float* W2   = (const float*)d_in[7];
    const float* b2   = (const float*)d_in[8];
    const float* W3   = (const float*)d_in[9];
    const float* b3   = (const float*)d_in[10];
    float* out = (float*)d_out;

    const int B = in_sizes[0] / 3;   // 1048576 = 8192 * 128 exactly

    pack_weights<<<1, 128>>>(W_ih, W_hh, b_ih, b_hh, W1, b1, W2, b2, W3, b3);

    void* wbuf_dev = nullptr;
    cudaGetSymbolAddress(&wbuf_dev, g_wbuf);
    cudaMemcpyToSymbolAsync(cbuf, wbuf_dev, 240 * sizeof(float), 0,
                            cudaMemcpyDeviceToDevice, 0);

    rnn_hmma<<<B / 128, 128>>>(x, out);
}